// round 10
// baseline (speedup 1.0000x reference)
#include <cuda_runtime.h>
#include <cstdint>

#define N_NODES 100000
#define N_EDGES 1250000
#define DIM 64
#define NBASES 16
#define N_TILES ((N_NODES + 63) / 64)   // 1563
#define SCAN_BLOCKS 98                  // ceil(100000 / 1024)
#define WBLOCKS 17

// ---------------- scratch (device globals; no allocation allowed) ----------
__device__ int g_cnt[N_NODES];          // per-dst edge count; re-zeroed by apply_kernel
__device__ int g_ps[N_NODES];           // block-local exclusive prescan
__device__ int g_bsum[SCAN_BLOCKS];     // per-scan-block totals
__device__ int g_row_ptr[N_NODES + 1];  // CSR row pointers (by dst)
__device__ int g_cursor[N_NODES];       // fill cursors for reorder
__device__ int g_esrc[N_EDGES];         // src index of each edge, grouped by dst
__device__ __align__(16) float2 g_Bp[64 * 64];  // k-pair-packed B
__device__ float g_bm[DIM];
__device__ float g_bs[DIM];

// packed f32x2 FMA: d.lo += a.lo*b.lo ; d.hi += a.hi*b.hi
__device__ __forceinline__ void fma2(unsigned long long& d,
                                     unsigned long long a,
                                     unsigned long long b) {
    asm("fma.rn.f32x2 %0, %1, %2, %0;" : "+l"(d) : "l"(a), "l"(b));
}
__device__ __forceinline__ float pair_sum(unsigned long long v) {
    return __uint_as_float((unsigned)(v & 0xffffffffull)) +
           __uint_as_float((unsigned)(v >> 32));
}
__device__ __forceinline__ void acc4(float4& a, const float4 v) {
    a.x += v.x; a.y += v.y; a.z += v.z; a.w += v.w;
}

// ---------------- kernel 1: weights (blocks 0..16) + dst histogram (rest) --
__global__ __launch_bounds__(256) void front_kernel(
    const int* __restrict__ ei,
    const float* __restrict__ wm, const float* __restrict__ bm,
    const float* __restrict__ ws, const float* __restrict__ bs,
    const float* __restrict__ lc) {
    if (blockIdx.x >= WBLOCKS) {                  // histogram of dst
        int t = (blockIdx.x - WBLOCKS) * 256 + threadIdx.x;
        if (t < N_EDGES) atomicAdd(&g_cnt[__ldg(&ei[N_EDGES + t])], 1);
        return;
    }
    __shared__ float c[NBASES];
    if (threadIdx.x < NBASES) c[threadIdx.x] = lc[threadIdx.x];
    __syncthreads();
    if (blockIdx.x < 16) {
        int idx = blockIdx.x * 256 + threadIdx.x;   // 0..4095
        int kp = idx >> 6;
        int o  = idx & 63;
        const float* base = (kp < 32) ? wm : ws;
        int i0 = (kp < 32) ? 2 * kp : 2 * (kp - 32);
        const float4* p0 = reinterpret_cast<const float4*>(&base[((size_t)i0 * 64 + o) * NBASES]);
        const float4* p1 = reinterpret_cast<const float4*>(&base[((size_t)(i0 + 1) * 64 + o) * NBASES]);
        float lo = 0.f, hi = 0.f;
        #pragma unroll
        for (int q = 0; q < 4; q++) {
            float4 a0 = __ldg(&p0[q]);
            float4 a1 = __ldg(&p1[q]);
            lo = fmaf(a0.x, c[4*q+0], lo); lo = fmaf(a0.y, c[4*q+1], lo);
            lo = fmaf(a0.z, c[4*q+2], lo); lo = fmaf(a0.w, c[4*q+3], lo);
            hi = fmaf(a1.x, c[4*q+0], hi); hi = fmaf(a1.y, c[4*q+1], hi);
            hi = fmaf(a1.z, c[4*q+2], hi); hi = fmaf(a1.w, c[4*q+3], hi);
        }
        g_Bp[idx] = make_float2(lo, hi);
    } else if (threadIdx.x < DIM) {
        int tid = threadIdx.x;
        float am = 0.f, as = 0.f;
        #pragma unroll
        for (int b = 0; b < NBASES; b++) {
            am = fmaf(__ldg(&bm[tid * NBASES + b]), c[b], am);
            as = fmaf(__ldg(&bs[tid * NBASES + b]), c[b], as);
        }
        g_bm[tid] = am;
        g_bs[tid] = as;
    }
}

// ---------------- kernel 2: per-block exclusive prescan of g_cnt -----------
__global__ __launch_bounds__(1024) void scan1_kernel() {
    __shared__ int wsum[32];
    int i = blockIdx.x * 1024 + threadIdx.x;
    int v = (i < N_NODES) ? g_cnt[i] : 0;
    int lane = threadIdx.x & 31, wid = threadIdx.x >> 5;
    int s = v;
    #pragma unroll
    for (int o = 1; o < 32; o <<= 1) {
        int t = __shfl_up_sync(0xffffffffu, s, o);
        if (lane >= o) s += t;
    }
    if (lane == 31) wsum[wid] = s;
    __syncthreads();
    if (wid == 0) {
        int ws = wsum[lane];
        #pragma unroll
        for (int o = 1; o < 32; o <<= 1) {
            int t = __shfl_up_sync(0xffffffffu, ws, o);
            if (lane >= o) ws += t;
        }
        wsum[lane] = ws;
    }
    __syncthreads();
    int woff = (wid > 0) ? wsum[wid - 1] : 0;
    if (i < N_NODES) g_ps[i] = woff + s - v;       // exclusive
    if (threadIdx.x == 1023) g_bsum[blockIdx.x] = wsum[31];
}

// ---------------- kernel 3: apply (inline bsum scan) -> row_ptr/cursor -----
// Each block redundantly scans the 98 block totals in smem (cheap), removing
// the separate scan2 launch (measured 4.5us of pure overhead in round 9).
__global__ __launch_bounds__(256) void apply_kernel() {
    __shared__ int sboff[SCAN_BLOCKS];
    __shared__ int wtot[4];
    int tid = threadIdx.x;
    int lane = tid & 31, wid = tid >> 5;
    int v = 0, s = 0;
    if (wid < 4) {                                  // warps 0..3: scan 128 slots
        v = (tid < SCAN_BLOCKS) ? g_bsum[tid] : 0;
        s = v;
        #pragma unroll
        for (int o = 1; o < 32; o <<= 1) {
            int t = __shfl_up_sync(0xffffffffu, s, o);
            if (lane >= o) s += t;
        }
        if (lane == 31) wtot[wid] = s;
    }
    __syncthreads();
    if (wid < 4 && tid < SCAN_BLOCKS) {
        int woff = 0;
        #pragma unroll
        for (int j = 0; j < 4; j++) if (j < wid) woff += wtot[j];
        sboff[tid] = woff + s - v;                  // exclusive scan of bsum
    }
    __syncthreads();
    int i = blockIdx.x * 256 + tid;
    if (i < N_NODES) {
        int rp = g_ps[i] + sboff[i >> 10];
        g_row_ptr[i] = rp;
        g_cursor[i]  = rp;
        g_cnt[i]     = 0;                           // ready for next call
    }
    if (i == 0) g_row_ptr[N_NODES] = N_EDGES;
}

// ---------------- kernel 4: reorder edge srcs into dst-grouped CSR ---------
__global__ __launch_bounds__(256) void reorder_kernel(const int* __restrict__ ei) {
    int t = blockIdx.x * 256 + threadIdx.x;
    if (t >= N_EDGES) return;
    int src = __ldg(&ei[t]);
    int dst = __ldg(&ei[N_EDGES + t]);
    int pos = atomicAdd(&g_cursor[dst], 1);
    g_esrc[pos] = src;
}

// ---------------- kernel 5: fused gather + GEMM + bias + L2-normalize ------
// Phase 1 (MLP-4): 64 node-groups x 4 threads; 4 edges per iteration — each
// thread loads one src, shfl(width=4) broadcasts, then up to 16 independent
// LDG.128 per thread before accumulating. Kills the serial per-edge chain
// that made round 9's gather latency-bound.
// Phase 2: f32x2 GEMM, aggregate half from smem, x half + B from L2/L1.
__global__ __launch_bounds__(256, 2) void gather_gemm_kernel(
    const float* __restrict__ x, float* __restrict__ out) {
    __shared__ __align__(16) float sAgg[64 * 64];  // 16KB aggregate tile
    __shared__ float sdeg[64];

    const int tid = threadIdx.x;
    const int node0 = blockIdx.x * 64;
    const float4* __restrict__ x4 = reinterpret_cast<const float4*>(x);

    // ---- Phase 1: gather (4 threads per node, 4-edge unroll) ----
    {
        const int g = tid >> 2;          // node group 0..63
        const int q = tid & 3;           // quarter of the 64-float row
        const int node = node0 + g;
        const unsigned gmask = 0xFu << (tid & 28);  // this group's 4 lanes
        float4 a0 = make_float4(0.f, 0.f, 0.f, 0.f), a1 = a0, a2 = a0, a3 = a0;
        if (node < N_NODES) {
            const int start = __ldg(&g_row_ptr[node]);
            const int end   = __ldg(&g_row_ptr[node + 1]);
            if (q == 0) sdeg[g] = (float)(end - start);
            for (int e = start; e < end; e += 4) {
                int mye = e + q;
                int sq = (mye < end) ? __ldg(&g_esrc[mye]) : -1;
                int s0 = __shfl_sync(gmask, sq, 0, 4);
                int s1 = __shfl_sync(gmask, sq, 1, 4);
                int s2 = __shfl_sync(gmask, sq, 2, 4);
                int s3 = __shfl_sync(gmask, sq, 3, 4);
                if (s0 >= 0) {
                    const float4* p = &x4[(size_t)s0 * 16 + q * 4];
                    acc4(a0, __ldg(p)); acc4(a1, __ldg(p+1)); acc4(a2, __ldg(p+2)); acc4(a3, __ldg(p+3));
                }
                if (s1 >= 0) {
                    const float4* p = &x4[(size_t)s1 * 16 + q * 4];
                    acc4(a0, __ldg(p)); acc4(a1, __ldg(p+1)); acc4(a2, __ldg(p+2)); acc4(a3, __ldg(p+3));
                }
                if (s2 >= 0) {
                    const float4* p = &x4[(size_t)s2 * 16 + q * 4];
                    acc4(a0, __ldg(p)); acc4(a1, __ldg(p+1)); acc4(a2, __ldg(p+2)); acc4(a3, __ldg(p+3));
                }
                if (s3 >= 0) {
                    const float4* p = &x4[(size_t)s3 * 16 + q * 4];
                    acc4(a0, __ldg(p)); acc4(a1, __ldg(p+1)); acc4(a2, __ldg(p+2)); acc4(a3, __ldg(p+3));
                }
            }
        } else if (q == 0) sdeg[g] = 0.f;
        float4* sa = reinterpret_cast<float4*>(&sAgg[g * 64 + q * 16]);
        sa[0] = a0; sa[1] = a1; sa[2] = a2; sa[3] = a3;
    }
    __syncthreads();

    // ---- Phase 2: GEMM ----
    const int jj = tid & 15;   // column group: cols j0..j0+3
    const int nn = tid >> 4;   // row group:   rows n0..n0+3
    const int j0 = jj * 4;
    const int n0 = nn * 4;

    const ulonglong2* A1 = reinterpret_cast<const ulonglong2*>(sAgg);  // 16 ull2/row
    const ulonglong2* __restrict__ X2  = reinterpret_cast<const ulonglong2*>(x);
    const ulonglong2* __restrict__ Bp2 = reinterpret_cast<const ulonglong2*>(g_Bp);
    const int bbase = j0 >> 1;

    int node[4];
    #pragma unroll
    for (int r = 0; r < 4; r++)
        node[r] = min(node0 + n0 + r, N_NODES - 1);  // clamp; uniform per 16-lane group

    unsigned long long acc[4][4];
    #pragma unroll
    for (int r = 0; r < 4; r++)
        #pragma unroll
        for (int c2 = 0; c2 < 4; c2++) acc[r][c2] = 0ull;

    // K half 1: A = aggregate rows (smem), B pair-rows kp 0..31
    #pragma unroll 4
    for (int k4 = 0; k4 < 16; k4++) {
        ulonglong2 av[4];
        #pragma unroll
        for (int r = 0; r < 4; r++)
            av[r] = A1[(n0 + r) * 16 + k4];
        #pragma unroll
        for (int p = 0; p < 2; p++) {
            int kp = k4 * 2 + p;
            ulonglong2 b01 = __ldg(&Bp2[kp * 32 + bbase]);
            ulonglong2 b23 = __ldg(&Bp2[kp * 32 + bbase + 1]);
            #pragma unroll
            for (int r = 0; r < 4; r++) {
                unsigned long long a = p ? av[r].y : av[r].x;
                fma2(acc[r][0], a, b01.x);
                fma2(acc[r][1], a, b01.y);
                fma2(acc[r][2], a, b23.x);
                fma2(acc[r][3], a, b23.y);
            }
        }
    }
    // K half 2: A = x rows (global), B pair-rows kp 32..63
    #pragma unroll 4
    for (int k4 = 0; k4 < 16; k4++) {
        ulonglong2 av[4];
        #pragma unroll
        for (int r = 0; r < 4; r++)
            av[r] = __ldg(&X2[(size_t)node[r] * 16 + k4]);
        #pragma unroll
        for (int p = 0; p < 2; p++) {
            int kp = 32 + k4 * 2 + p;
            ulonglong2 b01 = __ldg(&Bp2[kp * 32 + bbase]);
            ulonglong2 b23 = __ldg(&Bp2[kp * 32 + bbase + 1]);
            #pragma unroll
            for (int r = 0; r < 4; r++) {
                unsigned long long a = p ? av[r].y : av[r].x;
                fma2(acc[r][0], a, b01.x);
                fma2(acc[r][1], a, b01.y);
                fma2(acc[r][2], a, b23.x);
                fma2(acc[r][3], a, b23.y);
            }
        }
    }

    // biases for this thread's 4 columns
    float bmj[4], bsj[4];
    #pragma unroll
    for (int c = 0; c < 4; c++) {
        bmj[c] = __ldg(&g_bm[j0 + c]);
        bsj[c] = __ldg(&g_bs[j0 + c]);
    }

    // Epilogue: fold halves, bias, row L2-norm (across 16 jj lanes), store.
    #pragma unroll
    for (int r = 0; r < 4; r++) {
        float deg = sdeg[n0 + r];
        float o[4];
        #pragma unroll
        for (int c = 0; c < 4; c++)
            o[c] = pair_sum(acc[r][c]) + deg * bmj[c] + bsj[c];
        float ss = o[0] * o[0] + o[1] * o[1] + o[2] * o[2] + o[3] * o[3];
        #pragma unroll
        for (int off = 8; off > 0; off >>= 1)
            ss += __shfl_xor_sync(0xffffffffu, ss, off);
        float inv = 1.0f / fmaxf(sqrtf(ss), 1e-12f);
        if (node0 + n0 + r < N_NODES) {
            float4 ov = make_float4(o[0] * inv, o[1] * inv, o[2] * inv, o[3] * inv);
            reinterpret_cast<float4*>(out)[(size_t)node[r] * 16 + jj] = ov;
        }
    }
}

// ---------------- launch ----------------------------------------------------
extern "C" void kernel_launch(void* const* d_in, const int* in_sizes, int n_in,
                              void* d_out, int out_size) {
    const float* x  = (const float*)d_in[0];
    const int*   ei = (const int*)d_in[1];
    const float* wm = (const float*)d_in[2];
    const float* bm = (const float*)d_in[3];
    const float* ws = (const float*)d_in[4];
    const float* bs = (const float*)d_in[5];
    const float* lc = (const float*)d_in[6];
    float* out = (float*)d_out;

    const int eblocks = (N_EDGES + 255) / 256;
    const int nblocks = (N_NODES + 255) / 256;

    front_kernel<<<WBLOCKS + eblocks, 256>>>(ei, wm, bm, ws, bs, lc);  // weights + hist
    scan1_kernel<<<SCAN_BLOCKS, 1024>>>();
    apply_kernel<<<nblocks, 256>>>();              // row_ptr + cursor (inline bsum scan)
    reorder_kernel<<<eblocks, 256>>>(ei);          // dst-grouped src list
    gather_gemm_kernel<<<N_TILES, 256>>>(x, out);  // gather + GEMM + normalize
}